// round 11
// baseline (speedup 1.0000x reference)
#include <cuda_runtime.h>
#include <cuda_fp16.h>
#include <cstdint>

#define NF   128
#define HID  256
#define NTH  256
#define BM   128

// smem (halves). Pitches: 72 halves = 144B = 9x16B ; 264 halves = 528B = 33x16B
#define AW    72            // A chunk [128 r][64 k]
#define BW    72            // B chunks [n][64 k]
#define HWD   264           // H [128 r][256 k]

#define A_SZ   (128 * AW)       // 9216 halves / buffer (x2)
#define B1_SZ  (256 * BW)       // 18432 (x3)
#define B2_SZ  (128 * BW)       // 9216 (x3)
#define H_SZ   (128 * HWD)      // 33792

#define OFF_A   0
#define OFF_B1  (2 * A_SZ)              // 18432
#define OFF_H   0                        // phase2 overlays phase-1 region
#define OFF_B2  H_SZ                     // 33792 ; +3*B2_SZ = 61440 < 73728
#define SMEM_HALVES (OFF_B1 + 3 * B1_SZ) // 73728
#define SMEM_BYTES  (SMEM_HALVES * 2)    // 147456

// preconverted/transposed weights: W1T[n][k] 256x384, W2T[n][k] 128x256
__device__ __half g_W1T[256 * 384];
__device__ __half g_W2T[128 * 256];

// ---------------------------------------------------------------------------
static __device__ __forceinline__ uint32_t s2u(const void* p){
    uint32_t a;
    asm("{ .reg .u64 t; cvta.to.shared.u64 t, %1; cvt.u32.u64 %0, t; }" : "=r"(a) : "l"(p));
    return a;
}
static __device__ __forceinline__ void cp16(uint32_t d, const void* g){
    asm volatile("cp.async.ca.shared.global [%0], [%1], 16;" :: "r"(d), "l"(g) : "memory");
}
static __device__ __forceinline__ void cp_commit(){
    asm volatile("cp.async.commit_group;" ::: "memory");
}
static __device__ __forceinline__ void cp_wait1(){
    asm volatile("cp.async.wait_group 1;" ::: "memory");
}
static __device__ __forceinline__ void cp_wait0(){
    asm volatile("cp.async.wait_group 0;" ::: "memory");
}
// 4x 8x8 b16 matrices, non-transposed
static __device__ __forceinline__ void ldsm4(uint32_t* r, uint32_t addr){
    asm volatile("ldmatrix.sync.aligned.m8n8.x4.shared.b16 {%0,%1,%2,%3}, [%4];"
        : "=r"(r[0]), "=r"(r[1]), "=r"(r[2]), "=r"(r[3]) : "r"(addr));
}
// D(f32x4) += A(f16 16x16) * B(f16 16x8)
static __device__ __forceinline__ void mma16(float* c, const uint32_t* a,
                                             uint32_t b0, uint32_t b1){
    asm volatile("mma.sync.aligned.m16n8k16.row.col.f32.f16.f16.f32 "
        "{%0,%1,%2,%3}, {%4,%5,%6,%7}, {%8,%9}, {%0,%1,%2,%3};"
        : "+f"(c[0]), "+f"(c[1]), "+f"(c[2]), "+f"(c[3])
        : "r"(a[0]), "r"(a[1]), "r"(a[2]), "r"(a[3]), "r"(b0), "r"(b1));
}
static __device__ __forceinline__ uint32_t pack2(float x, float y){
    __half2 h = __floats2half2_rn(x, y);
    return *reinterpret_cast<uint32_t*>(&h);
}

// ---------------------------------------------------------------------------
__global__ void prep_weights(const float* __restrict__ W1, const float* __restrict__ W2){
    const int i = blockIdx.x * blockDim.x + threadIdx.x;
    if (i < 384 * 256){
        int k = i >> 8, n = i & 255;
        g_W1T[n * 384 + k] = __float2half_rn(W1[i]);
    } else {
        int j = i - 384 * 256;
        if (j < 256 * 128){
            int k = j >> 7, n = j & 127;
            g_W2T[n * 256 + k] = __float2half_rn(W2[j]);
        }
    }
}

// ---------------------------------------------------------------------------
// fused edge-MLP: out = relu([src,dst,edge] @ W1 + b1) @ W2 + b2 + edge
// 8 warps; phase1 warp tile 64x64 (2M x 4N); phase2 32x64 (4M x 2N)
// ---------------------------------------------------------------------------
__global__ void __launch_bounds__(NTH, 1)
edge_mlp_h5(const float* __restrict__ src, const float* __restrict__ dst,
            const float* __restrict__ edg, const float* __restrict__ b1,
            const float* __restrict__ b2,  float* __restrict__ out, int E)
{
    extern __shared__ __half sh[];
    const uint32_t sb = s2u(sh);
    __half* Ah  = sh + OFF_A;
    __half* Hh  = sh + OFF_H;

    const int tid  = threadIdx.x;
    const int lane = tid & 31, wid = tid >> 5;
    const int g = lane >> 2, t = lane & 3;
    const int row0 = blockIdx.x * BM;

    // ---- staging helpers (K-chunk = 64, A staged in 64-row halves) ----
    auto ldgAh = [&](int c, int h, float4* v){   // rows 64h..64h+63, 16 regs
        const float* xp = (c < 2) ? src : (c < 4) ? dst : edg;
        const int cb = (c & 1) * 64;
#pragma unroll
        for (int i = 0; i < 4; i++){
            int lin = tid + i * NTH;             // 0..1023
            int kq = lin & 15, r = (lin >> 4) + 64 * h;
            int rg = row0 + r;
            v[i] = (rg < E) ? *reinterpret_cast<const float4*>(
                                  xp + (size_t)rg * NF + cb + kq * 4)
                            : make_float4(0.f, 0.f, 0.f, 0.f);
        }
    };
    auto stsAh = [&](const float4* v, int h, int buf){
        __half* d = Ah + buf * A_SZ;
#pragma unroll
        for (int i = 0; i < 4; i++){
            int lin = tid + i * NTH;
            int kq = lin & 15, r = (lin >> 4) + 64 * h;
            uint2 p;
            p.x = pack2(v[i].x, v[i].y);
            p.y = pack2(v[i].z, v[i].w);
            *reinterpret_cast<uint2*>(d + r * AW + kq * 4) = p;
        }
    };
    auto cpB1 = [&](int c, int buf){             // W1T[n][c*64 .. +64]
        const uint32_t d = sb + (uint32_t)(OFF_B1 + buf * B1_SZ) * 2;
#pragma unroll
        for (int i = 0; i < 8; i++){
            int lin = tid + i * NTH;             // 0..2047
            int q = lin & 7, n = lin >> 3;
            cp16(d + (uint32_t)(n * BW + q * 8) * 2, g_W1T + n * 384 + c * 64 + q * 8);
        }
    };
    auto cpB2 = [&](int c, int buf){             // W2T[n][c*64 .. +64]
        const uint32_t d = sb + (uint32_t)(OFF_B2 + buf * B2_SZ) * 2;
#pragma unroll
        for (int i = 0; i < 4; i++){
            int lin = tid + i * NTH;             // 0..1023
            int q = lin & 7, n = lin >> 3;
            cp16(d + (uint32_t)(n * BW + q * 8) * 2, g_W2T + n * 256 + c * 64 + q * 8);
        }
    };

    // =================== phase 1: D1 = X @ W1  (K=384, 6 chunks) ===========
    const int rb = (wid & 1) * 64;               // 2M x 4N, tile 64x64
    const int nb = (wid >> 1) * 64;

    const uint32_t aOff = (uint32_t)(((rb + (lane & 15)) * AW + (lane >> 4) * 8)) * 2;
    const uint32_t bOff1 = (uint32_t)(((nb + (lane >> 4) * 8 + (lane & 7)) * BW
                                       + ((lane >> 3) & 1) * 8)) * 2;

    float acc[4][8][4];
#pragma unroll
    for (int ma = 0; ma < 4; ma++)
#pragma unroll
        for (int na = 0; na < 8; na++)
#pragma unroll
            for (int q = 0; q < 4; q++) acc[ma][na][q] = 0.f;

    float4 av[4];
    ldgAh(0, 0, av); stsAh(av, 0, 0);            // chunk 0 -> buf0
    ldgAh(0, 1, av); stsAh(av, 1, 0);
    cpB1(0, 0); cp_commit();
    cpB1(1, 1); cp_commit();

    for (int c = 0; c < 6; c++){
        const int p = c & 1;
        if (c < 5) cp_wait1(); else cp_wait0();   // B1 chunk c resident
        __syncthreads();                          // one barrier per chunk
        if (c < 4){ cpB1(c + 2, (c + 2) % 3); cp_commit(); }

        const uint32_t aB = sb + (uint32_t)(OFF_A + p * A_SZ) * 2 + aOff;
        const uint32_t bB = sb + (uint32_t)(OFF_B1 + (c % 3) * B1_SZ) * 2 + bOff1;
#pragma unroll
        for (int s = 0; s < 4; s++){
            uint32_t a[4][4], bf[4][4];
#pragma unroll
            for (int ma = 0; ma < 4; ma++)
                ldsm4(a[ma], aB + (uint32_t)(ma * 16 * AW) * 2 + s * 32);
#pragma unroll
            for (int q = 0; q < 4; q++)
                ldsm4(bf[q], bB + (uint32_t)(q * 16 * BW) * 2 + s * 32);
#pragma unroll
            for (int q = 0; q < 4; q++)
#pragma unroll
                for (int ma = 0; ma < 4; ma++){
                    mma16(acc[ma][2 * q + 0], a[ma], bf[q][0], bf[q][1]);
                    mma16(acc[ma][2 * q + 1], a[ma], bf[q][2], bf[q][3]);
                }
            // interleave A staging for chunk c+1 between MMA bursts
            if (c < 5){
                if (s == 0) ldgAh(c + 1, 0, av);
                else if (s == 1) stsAh(av, 0, p ^ 1);
                else if (s == 2) ldgAh(c + 1, 1, av);
                else stsAh(av, 1, p ^ 1);
            }
        }
    }
    __syncthreads();                              // phase-1 reads done (H overlays)

    // ====== epilogue 1: H = half(relu(D1 + b1)) -> smem (overlays) =========
    cpB2(0, 0); cp_commit();
#pragma unroll
    for (int na = 0; na < 8; na++){
        const int col = nb + na * 8 + 2 * t;
        const float2 bv = *reinterpret_cast<const float2*>(b1 + col);
#pragma unroll
        for (int ma = 0; ma < 4; ma++){
            const int r0 = rb + ma * 16 + g;
            *reinterpret_cast<uint32_t*>(Hh + r0 * HWD + col) =
                pack2(fmaxf(acc[ma][na][0] + bv.x, 0.f),
                      fmaxf(acc[ma][na][1] + bv.y, 0.f));
            *reinterpret_cast<uint32_t*>(Hh + (r0 + 8) * HWD + col) =
                pack2(fmaxf(acc[ma][na][2] + bv.x, 0.f),
                      fmaxf(acc[ma][na][3] + bv.y, 0.f));
        }
    }
    cpB2(1, 1); cp_commit();

    // =================== phase 2: D2 = H @ W2  (K=256, 4 chunks) ===========
    const int rb2 = (wid & 3) * 32;              // 4M x 2N, tile 32x64
    const int nb2 = (wid >> 2) * 64;

    const uint32_t aOff2 = (uint32_t)(((rb2 + (lane & 15)) * HWD + (lane >> 4) * 8)) * 2;
    const uint32_t bOff2 = (uint32_t)(((nb2 + (lane >> 4) * 8 + (lane & 7)) * BW
                                       + ((lane >> 3) & 1) * 8)) * 2;

    float ac2[2][8][4];
#pragma unroll
    for (int ma = 0; ma < 2; ma++)
#pragma unroll
        for (int na = 0; na < 8; na++)
#pragma unroll
            for (int q = 0; q < 4; q++) ac2[ma][na][q] = 0.f;

    for (int c2 = 0; c2 < 4; c2++){
        if (c2 < 3) cp_wait1(); else cp_wait0();  // B2 chunk c2 resident
        __syncthreads();                          // also fences H on c2==0
        if (c2 < 2){ cpB2(c2 + 2, (c2 + 2) % 3); cp_commit(); }
        const uint32_t aB = sb + (uint32_t)OFF_H * 2 + aOff2 + (uint32_t)(c2 * 64) * 2;
        const uint32_t bB = sb + (uint32_t)(OFF_B2 + (c2 % 3) * B2_SZ) * 2 + bOff2;
#pragma unroll
        for (int s = 0; s < 4; s++){
            uint32_t a[2][4], bf[4][4];
#pragma unroll
            for (int ma = 0; ma < 2; ma++)
                ldsm4(a[ma], aB + (uint32_t)(ma * 16 * HWD) * 2 + s * 32);
#pragma unroll
            for (int q = 0; q < 4; q++)
                ldsm4(bf[q], bB + (uint32_t)(q * 16 * BW) * 2 + s * 32);
#pragma unroll
            for (int q = 0; q < 4; q++)
#pragma unroll
                for (int ma = 0; ma < 2; ma++){
                    mma16(ac2[ma][2 * q + 0], a[ma], bf[q][0], bf[q][1]);
                    mma16(ac2[ma][2 * q + 1], a[ma], bf[q][2], bf[q][3]);
                }
        }
    }

    // ========= epilogue 2: out = D2 + b2 + edge residual (guarded) =========
#pragma unroll
    for (int ma = 0; ma < 2; ma++){
#pragma unroll
        for (int half = 0; half < 2; half++){
            const int rg = row0 + rb2 + ma * 16 + g + half * 8;
            if (rg < E){
#pragma unroll
                for (int na = 0; na < 8; na++){
                    const int col = nb2 + na * 8 + 2 * t;
                    const float2 bv = *reinterpret_cast<const float2*>(b2 + col);
                    const float2 ea = *reinterpret_cast<const float2*>(
                                          edg + (size_t)rg * NF + col);
                    float2 v;
                    v.x = ac2[ma][na][half * 2 + 0] + bv.x + ea.x;
                    v.y = ac2[ma][na][half * 2 + 1] + bv.y + ea.y;
                    *reinterpret_cast<float2*>(out + (size_t)rg * NF + col) = v;
                }
            }
        }
    }
}

// ---------------------------------------------------------------------------
// inputs: 0=src 1=dest 2=edge_attr 3=u(unused) 4=batch(unused) 5=W1 6=b1 7=W2 8=b2
// ---------------------------------------------------------------------------
extern "C" void kernel_launch(void* const* d_in, const int* in_sizes, int n_in,
                              void* d_out, int out_size)
{
    const float* src  = (const float*)d_in[0];
    const float* dst  = (const float*)d_in[1];
    const float* edge = (const float*)d_in[2];
    const float* W1   = (const float*)d_in[5];
    const float* b1   = (const float*)d_in[6];
    const float* W2   = (const float*)d_in[7];
    const float* b2   = (const float*)d_in[8];
    float* out = (float*)d_out;

    const int E = in_sizes[0] / NF;

    prep_weights<<<(384 * 256 + 256 * 128 + 255) / 256, 256>>>(W1, W2);

    cudaFuncSetAttribute(edge_mlp_h5,
                         cudaFuncAttributeMaxDynamicSharedMemorySize, SMEM_BYTES);
    const int grid = (E + BM - 1) / BM;
    edge_mlp_h5<<<grid, NTH, SMEM_BYTES>>>(src, dst, edge, b1, b2, out, E);
}

// round 12
// speedup vs baseline: 1.1311x; 1.1311x over previous
#include <cuda_runtime.h>
#include <cuda_fp16.h>
#include <cstdint>

#define NF   128
#define HID  256
#define NTH  256
#define BM   64

// smem (halves). Pitches: 72 = 9x16B ; 264 = 33x16B
#define AW    72            // A chunk [64 r][64 k]
#define BW    72            // B chunks [n][64 k]
#define HWD   264           // H [64 r][256 k]

#define A_SZ   (64 * AW)        // 4608 halves / buffer (x2)
#define B1_SZ  (256 * BW)       // 18432 (x2)
#define B2_SZ  (128 * BW)       // 9216 (x2)
#define H_SZ   (64 * HWD)       // 16896

#define OFF_A   0
#define OFF_B1  (2 * A_SZ)              // 9216
#define OFF_H   0                        // phase2 overlays phase-1 region
#define OFF_B2  H_SZ                     // 16896 ; +2*B2_SZ = 35328 < 46080
#define SMEM_HALVES (OFF_B1 + 2 * B1_SZ) // 46080
#define SMEM_BYTES  (SMEM_HALVES * 2)    // 92160  -> 2 CTAs/SM

// preconverted/transposed weights: W1T[n][k] 256x384, W2T[n][k] 128x256
__device__ __half g_W1T[256 * 384];
__device__ __half g_W2T[128 * 256];

// ---------------------------------------------------------------------------
static __device__ __forceinline__ uint32_t s2u(const void* p){
    uint32_t a;
    asm("{ .reg .u64 t; cvta.to.shared.u64 t, %1; cvt.u32.u64 %0, t; }" : "=r"(a) : "l"(p));
    return a;
}
static __device__ __forceinline__ void cp16(uint32_t d, const void* g){
    asm volatile("cp.async.ca.shared.global [%0], [%1], 16;" :: "r"(d), "l"(g) : "memory");
}
static __device__ __forceinline__ void cp_commit(){
    asm volatile("cp.async.commit_group;" ::: "memory");
}
static __device__ __forceinline__ void cp_wait1(){
    asm volatile("cp.async.wait_group 1;" ::: "memory");
}
static __device__ __forceinline__ void cp_wait0(){
    asm volatile("cp.async.wait_group 0;" ::: "memory");
}
// 4x 8x8 b16 matrices, non-transposed
static __device__ __forceinline__ void ldsm4(uint32_t* r, uint32_t addr){
    asm volatile("ldmatrix.sync.aligned.m8n8.x4.shared.b16 {%0,%1,%2,%3}, [%4];"
        : "=r"(r[0]), "=r"(r[1]), "=r"(r[2]), "=r"(r[3]) : "r"(addr));
}
// D(f32x4) += A(f16 16x16) * B(f16 16x8)
static __device__ __forceinline__ void mma16(float* c, const uint32_t* a,
                                             uint32_t b0, uint32_t b1){
    asm volatile("mma.sync.aligned.m16n8k16.row.col.f32.f16.f16.f32 "
        "{%0,%1,%2,%3}, {%4,%5,%6,%7}, {%8,%9}, {%0,%1,%2,%3};"
        : "+f"(c[0]), "+f"(c[1]), "+f"(c[2]), "+f"(c[3])
        : "r"(a[0]), "r"(a[1]), "r"(a[2]), "r"(a[3]), "r"(b0), "r"(b1));
}
static __device__ __forceinline__ uint32_t pack2(float x, float y){
    __half2 h = __floats2half2_rn(x, y);
    return *reinterpret_cast<uint32_t*>(&h);
}

// ---------------------------------------------------------------------------
__global__ void prep_weights(const float* __restrict__ W1, const float* __restrict__ W2){
    const int i = blockIdx.x * blockDim.x + threadIdx.x;
    if (i < 384 * 256){
        int k = i >> 8, n = i & 255;
        g_W1T[n * 384 + k] = __float2half_rn(W1[i]);
    } else {
        int j = i - 384 * 256;
        if (j < 256 * 128){
            int k = j >> 7, n = j & 127;
            g_W2T[n * 256 + k] = __float2half_rn(W2[j]);
        }
    }
}

// ---------------------------------------------------------------------------
// fused edge-MLP: out = relu([src,dst,edge] @ W1 + b1) @ W2 + b2 + edge
// BM=64 rows/CTA, 8 warps; phase1 tile 32x64 (2M x 4N); phase2 32x32 (2M x 4N)
// ---------------------------------------------------------------------------
__global__ void __launch_bounds__(NTH, 2)
edge_mlp_h6(const float* __restrict__ src, const float* __restrict__ dst,
            const float* __restrict__ edg, const float* __restrict__ b1,
            const float* __restrict__ b2,  float* __restrict__ out, int E)
{
    extern __shared__ __half sh[];
    const uint32_t sb = s2u(sh);
    __half* Ah  = sh + OFF_A;
    __half* Hh  = sh + OFF_H;

    const int tid  = threadIdx.x;
    const int lane = tid & 31, wid = tid >> 5;
    const int g = lane >> 2, t = lane & 3;
    const int row0 = blockIdx.x * BM;

    // ---- staging helpers (K-chunk = 64) ----
    auto ldgA = [&](int c, float4* v){           // X[64 r, c*64 .. +64] fp32
        const float* xp = (c < 2) ? src : (c < 4) ? dst : edg;
        const int cb = (c & 1) * 64;
#pragma unroll
        for (int i = 0; i < 4; i++){
            int lin = tid + i * NTH;             // 0..1023
            int kq = lin & 15, r = lin >> 4;     // 16 float4 x 64 rows
            int rg = row0 + r;
            v[i] = (rg < E) ? *reinterpret_cast<const float4*>(
                                  xp + (size_t)rg * NF + cb + kq * 4)
                            : make_float4(0.f, 0.f, 0.f, 0.f);
        }
    };
    auto stsA = [&](const float4* v, int buf){
        __half* d = Ah + buf * A_SZ;
#pragma unroll
        for (int i = 0; i < 4; i++){
            int lin = tid + i * NTH;
            int kq = lin & 15, r = lin >> 4;
            uint2 p;
            p.x = pack2(v[i].x, v[i].y);
            p.y = pack2(v[i].z, v[i].w);
            *reinterpret_cast<uint2*>(d + r * AW + kq * 4) = p;
        }
    };
    auto cpB1 = [&](int c, int buf){             // W1T[n][c*64 .. +64]
        const uint32_t d = sb + (uint32_t)(OFF_B1 + buf * B1_SZ) * 2;
#pragma unroll
        for (int i = 0; i < 8; i++){
            int lin = tid + i * NTH;             // 0..2047
            int q = lin & 7, n = lin >> 3;
            cp16(d + (uint32_t)(n * BW + q * 8) * 2, g_W1T + n * 384 + c * 64 + q * 8);
        }
    };
    auto cpB2 = [&](int c, int buf){             // W2T[n][c*64 .. +64]
        const uint32_t d = sb + (uint32_t)(OFF_B2 + buf * B2_SZ) * 2;
#pragma unroll
        for (int i = 0; i < 4; i++){
            int lin = tid + i * NTH;             // 0..1023
            int q = lin & 7, n = lin >> 3;
            cp16(d + (uint32_t)(n * BW + q * 8) * 2, g_W2T + n * 256 + c * 64 + q * 8);
        }
    };

    // =================== phase 1: D1 = X @ W1  (K=384, 6 chunks) ===========
    const int rb = (wid & 1) * 32;               // 2M x 4N, tile 32x64
    const int nb = (wid >> 1) * 64;

    const uint32_t aOff = (uint32_t)(((rb + (lane & 15)) * AW + (lane >> 4) * 8)) * 2;
    const uint32_t bOff1 = (uint32_t)(((nb + (lane >> 4) * 8 + (lane & 7)) * BW
                                       + ((lane >> 3) & 1) * 8)) * 2;

    float acc[2][8][4];
#pragma unroll
    for (int ma = 0; ma < 2; ma++)
#pragma unroll
        for (int na = 0; na < 8; na++)
#pragma unroll
            for (int q = 0; q < 4; q++) acc[ma][na][q] = 0.f;

    float4 av[4];
    ldgA(0, av); stsA(av, 0);                     // chunk 0 -> buf0
    ldgA(1, av);                                  // chunk 1 in regs
    cpB1(0, 0); cp_commit();
    cpB1(1, 1); cp_commit();

    for (int c = 0; c < 6; c++){
        const int p = c & 1;
        if (c < 5) cp_wait1(); else cp_wait0();   // B1 chunk c resident
        __syncthreads();
        const uint32_t aB = sb + (uint32_t)(OFF_A + p * A_SZ) * 2 + aOff;
        const uint32_t bB = sb + (uint32_t)(OFF_B1 + p * B1_SZ) * 2 + bOff1;
#pragma unroll
        for (int s = 0; s < 4; s++){
            uint32_t a[2][4], bf[4][4];
#pragma unroll
            for (int ma = 0; ma < 2; ma++)
                ldsm4(a[ma], aB + (uint32_t)(ma * 16 * AW) * 2 + s * 32);
#pragma unroll
            for (int q = 0; q < 4; q++)
                ldsm4(bf[q], bB + (uint32_t)(q * 16 * BW) * 2 + s * 32);
#pragma unroll
            for (int q = 0; q < 4; q++)
#pragma unroll
                for (int ma = 0; ma < 2; ma++){
                    mma16(acc[ma][2 * q + 0], a[ma], bf[q][0], bf[q][1]);
                    mma16(acc[ma][2 * q + 1], a[ma], bf[q][2], bf[q][3]);
                }
            // interleave A staging for chunk c+1 (other A buffer; no reader)
            if (c < 5){
                if (s == 1) stsA(av, p ^ 1);
                else if (s == 2 && c < 4) ldgA(c + 2, av);
            }
        }
        __syncthreads();                          // B1 buf p reads done
        if (c < 4){ cpB1(c + 2, p); cp_commit(); }
    }

    // ====== epilogue 1: H = half(relu(D1 + b1)) -> smem (overlays) =========
    cpB2(0, 0); cp_commit();
#pragma unroll
    for (int na = 0; na < 8; na++){
        const int col = nb + na * 8 + 2 * t;
        const float2 bv = *reinterpret_cast<const float2*>(b1 + col);
#pragma unroll
        for (int ma = 0; ma < 2; ma++){
            const int r0 = rb + ma * 16 + g;
            *reinterpret_cast<uint32_t*>(Hh + r0 * HWD + col) =
                pack2(fmaxf(acc[ma][na][0] + bv.x, 0.f),
                      fmaxf(acc[ma][na][1] + bv.y, 0.f));
            *reinterpret_cast<uint32_t*>(Hh + (r0 + 8) * HWD + col) =
                pack2(fmaxf(acc[ma][na][2] + bv.x, 0.f),
                      fmaxf(acc[ma][na][3] + bv.y, 0.f));
        }
    }
    cpB2(1, 1); cp_commit();

    // =================== phase 2: D2 = H @ W2  (K=256, 4 chunks) ===========
    const int rb2 = (wid & 1) * 32;              // 2M x 4N, tile 32x32
    const int nb2 = (wid >> 1) * 32;

    const uint32_t aOff2 = (uint32_t)(((rb2 + (lane & 15)) * HWD + (lane >> 4) * 8)) * 2;
    const uint32_t bOff2 = (uint32_t)(((nb2 + (lane >> 4) * 8 + (lane & 7)) * BW
                                       + ((lane >> 3) & 1) * 8)) * 2;

    float ac2[2][4][4];
#pragma unroll
    for (int ma = 0; ma < 2; ma++)
#pragma unroll
        for (int na = 0; na < 4; na++)
#pragma unroll
            for (int q = 0; q < 4; q++) ac2[ma][na][q] = 0.f;

    for (int c2 = 0; c2 < 4; c2++){
        const int p = c2 & 1;
        if (c2 < 3) cp_wait1(); else cp_wait0();  // B2 chunk c2 resident
        __syncthreads();                          // also fences H on c2==0
        const uint32_t aB = sb + (uint32_t)OFF_H * 2 + aOff2 + (uint32_t)(c2 * 64) * 2;
        const uint32_t bB = sb + (uint32_t)(OFF_B2 + p * B2_SZ) * 2 + bOff2;
#pragma unroll
        for (int s = 0; s < 4; s++){
            uint32_t a[2][4], bf[2][4];
#pragma unroll
            for (int ma = 0; ma < 2; ma++)
                ldsm4(a[ma], aB + (uint32_t)(ma * 16 * HWD) * 2 + s * 32);
#pragma unroll
            for (int q = 0; q < 2; q++)
                ldsm4(bf[q], bB + (uint32_t)(q * 16 * BW) * 2 + s * 32);
#pragma unroll
            for (int q = 0; q < 2; q++)
#pragma unroll
                for (int ma = 0; ma < 2; ma++){
                    mma16(ac2[ma][2 * q + 0], a[ma], bf[q][0], bf[q][1]);
                    mma16(ac2[ma][2 * q + 1], a[ma], bf[q][2], bf[q][3]);
                }
        }
        __syncthreads();                          // B2 buf p reads done
        if (c2 < 2){ cpB2(c2 + 2, p); cp_commit(); }
    }

    // ========= epilogue 2: out = D2 + b2 + edge residual (guarded) =========
#pragma unroll
    for (int ma = 0; ma < 2; ma++){
#pragma unroll
        for (int half = 0; half < 2; half++){
            const int rg = row0 + rb2 + ma * 16 + g + half * 8;
            if (rg < E){
#pragma unroll
                for (int na = 0; na < 4; na++){
                    const int col = nb2 + na * 8 + 2 * t;
                    const float2 bv = *reinterpret_cast<const float2*>(b2 + col);
                    const float2 ea = *reinterpret_cast<const float2*>(
                                          edg + (size_t)rg * NF + col);
                    float2 v;
                    v.x = ac2[ma][na][half * 2 + 0] + bv.x + ea.x;
                    v.y = ac2[ma][na][half * 2 + 1] + bv.y + ea.y;
                    *reinterpret_cast<float2*>(out + (size_t)rg * NF + col) = v;
                }
            }
        }
    }
}

// ---------------------------------------------------------------------------
// inputs: 0=src 1=dest 2=edge_attr 3=u(unused) 4=batch(unused) 5=W1 6=b1 7=W2 8=b2
// ---------------------------------------------------------------------------
extern "C" void kernel_launch(void* const* d_in, const int* in_sizes, int n_in,
                              void* d_out, int out_size)
{
    const float* src  = (const float*)d_in[0];
    const float* dst  = (const float*)d_in[1];
    const float* edge = (const float*)d_in[2];
    const float* W1   = (const float*)d_in[5];
    const float* b1   = (const float*)d_in[6];
    const float* W2   = (const float*)d_in[7];
    const float* b2   = (const float*)d_in[8];
    float* out = (float*)d_out;

    const int E = in_sizes[0] / NF;

    prep_weights<<<(384 * 256 + 256 * 128 + 255) / 256, 256>>>(W1, W2);

    cudaFuncSetAttribute(edge_mlp_h6,
                         cudaFuncAttributeMaxDynamicSharedMemorySize, SMEM_BYTES);
    const int grid = (E + BM - 1) / BM;
    edge_mlp_h6<<<grid, NTH, SMEM_BYTES>>>(src, dst, edge, b1, b2, out, E);
}

// round 13
// speedup vs baseline: 1.2610x; 1.1148x over previous
#include <cuda_runtime.h>
#include <cuda_fp16.h>
#include <cstdint>

#define NF   128
#define HID  256
#define NTH  256
#define BM   64

// smem (halves): A 2 buffers + H. No B in smem at all.
#define AW    72            // A chunk [64 r][64 k], pitch 72 (9x16B)
#define HWD   264           // H [64 r][256 k], pitch 264 (33x16B)
#define A_SZ  (64 * AW)         // 4608 halves per buffer (x2)
#define OFF_H (2 * A_SZ)        // 9216
#define SMEM_HALVES (OFF_H + 64 * HWD)   // 26112
#define SMEM_BYTES  (SMEM_HALVES * 2)    // 52224 -> 2 CTAs/SM easily

// fragment-ordered weights:
// W1F[wn(4)][c(6)][s(4)][q(4)][lane(32)] : uint4 = {b0,b1,b2,b3} per lane
// W2F[wn(4)][c(4)][s(4)][q(2)][lane(32)]
__device__ uint4 g_W1F[4 * 6 * 4 * 4 * 32];   // 12288
__device__ uint4 g_W2F[4 * 4 * 4 * 2 * 32];   // 4096

// ---------------------------------------------------------------------------
static __device__ __forceinline__ uint32_t s2u(const void* p){
    uint32_t a;
    asm("{ .reg .u64 t; cvta.to.shared.u64 t, %1; cvt.u32.u64 %0, t; }" : "=r"(a) : "l"(p));
    return a;
}
static __device__ __forceinline__ void ldsm4(uint32_t* r, uint32_t addr){
    asm volatile("ldmatrix.sync.aligned.m8n8.x4.shared.b16 {%0,%1,%2,%3}, [%4];"
        : "=r"(r[0]), "=r"(r[1]), "=r"(r[2]), "=r"(r[3]) : "r"(addr));
}
static __device__ __forceinline__ void mma16(float* c, const uint32_t* a,
                                             uint32_t b0, uint32_t b1){
    asm volatile("mma.sync.aligned.m16n8k16.row.col.f32.f16.f16.f32 "
        "{%0,%1,%2,%3}, {%4,%5,%6,%7}, {%8,%9}, {%0,%1,%2,%3};"
        : "+f"(c[0]), "+f"(c[1]), "+f"(c[2]), "+f"(c[3])
        : "r"(a[0]), "r"(a[1]), "r"(a[2]), "r"(a[3]), "r"(b0), "r"(b1));
}
static __device__ __forceinline__ uint32_t pack2(float x, float y){
    __half2 h = __floats2half2_rn(x, y);
    return *reinterpret_cast<uint32_t*>(&h);
}

// ---------------------------------------------------------------------------
// prep: permute W1[384,256] / W2[256,128] (k-major fp32) into fragment order.
// lane holds: n0 = base + q*16 + (lane>>2), k0 = c*64 + s*16 + 2*(lane&3)
//   v.x = {W[k0][n0],   W[k0+1][n0]}    (b0: k pair, n-tile 2q)
//   v.y = {W[k0+8][n0], W[k0+9][n0]}    (b1)
//   v.z/v.w = same at n0+8              (n-tile 2q+1)
// ---------------------------------------------------------------------------
__global__ void prep_frag(const float* __restrict__ W1, const float* __restrict__ W2){
    const int i = blockIdx.x * blockDim.x + threadIdx.x;
    if (i < 12288){
        int lane = i & 31;
        int q = (i >> 5) & 3;
        int s = (i >> 7) & 3;
        int cw = i >> 9;               // wn*6 + c
        int c = cw % 6, wn = cw / 6;
        int n0 = wn * 64 + q * 16 + (lane >> 2);
        int k0 = c * 64 + s * 16 + 2 * (lane & 3);
        uint4 v;
        v.x = pack2(W1[(size_t)k0 * HID + n0],       W1[(size_t)(k0 + 1) * HID + n0]);
        v.y = pack2(W1[(size_t)(k0 + 8) * HID + n0], W1[(size_t)(k0 + 9) * HID + n0]);
        v.z = pack2(W1[(size_t)k0 * HID + n0 + 8],       W1[(size_t)(k0 + 1) * HID + n0 + 8]);
        v.w = pack2(W1[(size_t)(k0 + 8) * HID + n0 + 8], W1[(size_t)(k0 + 9) * HID + n0 + 8]);
        g_W1F[i] = v;
    } else if (i < 12288 + 4096){
        int j = i - 12288;
        int lane = j & 31;
        int q = (j >> 5) & 1;
        int s = (j >> 6) & 3;
        int c = (j >> 8) & 3;
        int wn = (j >> 10) & 3;
        int n0 = wn * 32 + q * 16 + (lane >> 2);
        int k0 = c * 64 + s * 16 + 2 * (lane & 3);
        uint4 v;
        v.x = pack2(W2[(size_t)k0 * NF + n0],       W2[(size_t)(k0 + 1) * NF + n0]);
        v.y = pack2(W2[(size_t)(k0 + 8) * NF + n0], W2[(size_t)(k0 + 9) * NF + n0]);
        v.z = pack2(W2[(size_t)k0 * NF + n0 + 8],       W2[(size_t)(k0 + 1) * NF + n0 + 8]);
        v.w = pack2(W2[(size_t)(k0 + 8) * NF + n0 + 8], W2[(size_t)(k0 + 9) * NF + n0 + 8]);
        g_W2F[j] = v;
    }
}

// ---------------------------------------------------------------------------
// fused edge-MLP: out = relu([src,dst,edge] @ W1 + b1) @ W2 + b2 + edge
// BM=64, 8 warps, 2 CTAs/SM. B operands: direct LDG.128 in fragment order.
// ---------------------------------------------------------------------------
__global__ void __launch_bounds__(NTH, 2)
edge_mlp_h7(const float* __restrict__ src, const float* __restrict__ dst,
            const float* __restrict__ edg, const float* __restrict__ b1,
            const float* __restrict__ b2,  float* __restrict__ out, int E)
{
    extern __shared__ __half sh[];
    const uint32_t sb = s2u(sh);
    __half* Ah = sh;                 // 2 x A_SZ
    __half* Hh = sh + OFF_H;         // 64 x HWD

    const int tid  = threadIdx.x;
    const int lane = tid & 31, wid = tid >> 5;
    const int g = lane >> 2, t = lane & 3;
    const int row0 = blockIdx.x * BM;

    // ---- A staging (K-chunk = 64) ----
    auto ldgA = [&](int c, float4* v){           // X[64 r, c*64 .. +64] fp32
        const float* xp = (c < 2) ? src : (c < 4) ? dst : edg;
        const int cb = (c & 1) * 64;
#pragma unroll
        for (int i = 0; i < 4; i++){
            int lin = tid + i * NTH;             // 0..1023
            int kq = lin & 15, r = lin >> 4;
            int rg = row0 + r;
            v[i] = (rg < E) ? *reinterpret_cast<const float4*>(
                                  xp + (size_t)rg * NF + cb + kq * 4)
                            : make_float4(0.f, 0.f, 0.f, 0.f);
        }
    };
    auto stsA = [&](const float4* v, int buf){
        __half* d = Ah + buf * A_SZ;
#pragma unroll
        for (int i = 0; i < 4; i++){
            int lin = tid + i * NTH;
            int kq = lin & 15, r = lin >> 4;
            uint2 p;
            p.x = pack2(v[i].x, v[i].y);
            p.y = pack2(v[i].z, v[i].w);
            *reinterpret_cast<uint2*>(d + r * AW + kq * 4) = p;
        }
    };

    // =================== phase 1: D1 = X @ W1  (K=384, 6 chunks) ===========
    const int rb = (wid & 1) * 32;               // 2M x 4N, warp tile 32x64
    const int wn = wid >> 1;
    const int nb = wn * 64;

    const uint32_t aOff = (uint32_t)(((rb + (lane & 15)) * AW + (lane >> 4) * 8)) * 2;

    float acc[2][8][4];
#pragma unroll
    for (int ma = 0; ma < 2; ma++)
#pragma unroll
        for (int na = 0; na < 8; na++)
#pragma unroll
            for (int q = 0; q < 4; q++) acc[ma][na][q] = 0.f;

    float4 av[4];
    ldgA(0, av); stsA(av, 0);                    // chunk 0 -> buf0
    ldgA(1, av);                                 // chunk 1 in regs

    for (int c = 0; c < 6; c++){
        const int p = c & 1;
        __syncthreads();                         // A buf p complete; p^1 free
        const uint32_t aB = sb + (uint32_t)(p * A_SZ) * 2 + aOff;
        const uint4* bp = g_W1F + (size_t)((wn * 6 + c) * 16) * 32 + lane;
#pragma unroll
        for (int s = 0; s < 4; s++){
            uint32_t a[2][4];
#pragma unroll
            for (int ma = 0; ma < 2; ma++)
                ldsm4(a[ma], aB + (uint32_t)(ma * 16 * AW) * 2 + s * 32);
            uint4 v0 = bp[(s * 4 + 0) * 32];
            uint4 v1 = bp[(s * 4 + 1) * 32];
            uint4 v2 = bp[(s * 4 + 2) * 32];
            uint4 v3 = bp[(s * 4 + 3) * 32];
#pragma unroll
            for (int ma = 0; ma < 2; ma++){
                mma16(acc[ma][0], a[ma], v0.x, v0.y);
                mma16(acc[ma][1], a[ma], v0.z, v0.w);
                mma16(acc[ma][2], a[ma], v1.x, v1.y);
                mma16(acc[ma][3], a[ma], v1.z, v1.w);
                mma16(acc[ma][4], a[ma], v2.x, v2.y);
                mma16(acc[ma][5], a[ma], v2.z, v2.w);
                mma16(acc[ma][6], a[ma], v3.x, v3.y);
                mma16(acc[ma][7], a[ma], v3.z, v3.w);
            }
            if (c < 5){
                if (s == 1) stsA(av, p ^ 1);            // chunk c+1 -> free buf
                else if (s == 2 && c < 4) ldgA(c + 2, av);
            }
        }
    }

    // ====== epilogue 1: H = half(relu(D1 + b1)) -> smem (disjoint) =========
#pragma unroll
    for (int na = 0; na < 8; na++){
        const int col = nb + na * 8 + 2 * t;
        const float2 bv = *reinterpret_cast<const float2*>(b1 + col);
#pragma unroll
        for (int ma = 0; ma < 2; ma++){
            const int r0 = rb + ma * 16 + g;
            *reinterpret_cast<uint32_t*>(Hh + r0 * HWD + col) =
                pack2(fmaxf(acc[ma][na][0] + bv.x, 0.f),
                      fmaxf(acc[ma][na][1] + bv.y, 0.f));
            *reinterpret_cast<uint32_t*>(Hh + (r0 + 8) * HWD + col) =
                pack2(fmaxf(acc[ma][na][2] + bv.x, 0.f),
                      fmaxf(acc[ma][na][3] + bv.y, 0.f));
        }
    }
    __syncthreads();                             // H visible to all warps

    // =================== phase 2: D2 = H @ W2  (K=256, no barriers) ========
    const int rb2 = (wid & 1) * 32;              // 2M x 4N, warp tile 32x32
    const int wn2 = wid >> 1;
    const int nb2 = wn2 * 32;

    const uint32_t aOff2 = (uint32_t)(((rb2 + (lane & 15)) * HWD + (lane >> 4) * 8)) * 2;

    float ac2[2][4][4];
#pragma unroll
    for (int ma = 0; ma < 2; ma++)
#pragma unroll
        for (int na = 0; na < 4; na++)
#pragma unroll
            for (int q = 0; q < 4; q++) ac2[ma][na][q] = 0.f;

#pragma unroll
    for (int c2 = 0; c2 < 4; c2++){
        const uint32_t aB = sb + (uint32_t)OFF_H * 2 + aOff2 + (uint32_t)(c2 * 64) * 2;
        const uint4* bp = g_W2F + (size_t)((wn2 * 4 + c2) * 8) * 32 + lane;
#pragma unroll
        for (int s = 0; s < 4; s++){
            uint32_t a[2][4];
#pragma unroll
            for (int ma = 0; ma < 2; ma++)
                ldsm4(a[ma], aB + (uint32_t)(ma * 16 * HWD) * 2 + s * 32);
            uint4 v0 = bp[(s * 2 + 0) * 32];
            uint4 v1 = bp[(s * 2 + 1) * 32];
#pragma unroll
            for (int ma = 0; ma < 2; ma++){
                mma16(ac2[ma][0], a[ma], v0.x, v0.y);
                mma16(ac2[ma][1], a[ma], v0.z, v0.w);
                mma16(ac2[ma][2], a[ma], v1.x, v1.y);
                mma16(ac2[ma][3], a[ma], v1.z, v1.w);
            }
        }
    }

    // ========= epilogue 2: out = D2 + b2 + edge residual (guarded) =========
#pragma unroll
    for (int ma = 0; ma < 2; ma++){
#pragma unroll
        for (int half = 0; half < 2; half++){
            const int rg = row0 + rb2 + ma * 16 + g + half * 8;
            if (rg < E){
#pragma unroll
                for (int na = 0; na < 4; na++){
                    const int col = nb2 + na * 8 + 2 * t;
                    const float2 bv = *reinterpret_cast<const float2*>(b2 + col);
                    const float2 ea = *reinterpret_cast<const float2*>(
                                          edg + (size_t)rg * NF + col);
                    float2 v;
                    v.x = ac2[ma][na][half * 2 + 0] + bv.x + ea.x;
                    v.y = ac2[ma][na][half * 2 + 1] + bv.y + ea.y;
                    *reinterpret_cast<float2*>(out + (size_t)rg * NF + col) = v;
                }
            }
        }
    }
}

// ---------------------------------------------------------------------------
// inputs: 0=src 1=dest 2=edge_attr 3=u(unused) 4=batch(unused) 5=W1 6=b1 7=W2 8=b2
// ---------------------------------------------------------------------------
extern "C" void kernel_launch(void* const* d_in, const int* in_sizes, int n_in,
                              void* d_out, int out_size)
{
    const float* src  = (const float*)d_in[0];
    const float* dst  = (const float*)d_in[1];
    const float* edge = (const float*)d_in[2];
    const float* W1   = (const float*)d_in[5];
    const float* b1   = (const float*)d_in[6];
    const float* W2   = (const float*)d_in[7];
    const float* b2   = (const float*)d_in[8];
    float* out = (float*)d_out;

    const int E = in_sizes[0] / NF;

    prep_frag<<<(12288 + 4096 + 255) / 256, 256>>>(W1, W2);

    cudaFuncSetAttribute(edge_mlp_h7,
                         cudaFuncAttributeMaxDynamicSharedMemorySize, SMEM_BYTES);
    const int grid = (E + BM - 1) / BM;
    edge_mlp_h7<<<grid, NTH, SMEM_BYTES>>>(src, dst, edge, b1, b2, out, E);
}